// round 16
// baseline (speedup 1.0000x reference)
#include <cuda_runtime.h>
#include <cstdint>

#define NN 16384
#define CAP 96

// Scratch (no allocations). Referenced ONLY from device code.
__device__ int   g_cnt[NN];
__device__ int   g_nbr[NN * CAP];
__device__ float g_z[NN * 128];
__device__ float g_r[NN * 128];
__device__ float g_h[NN * 128];

__global__ void zero_cnt_kernel() {
    int i = blockIdx.x * blockDim.x + threadIdx.x;
    if (i < NN) g_cnt[i] = 0;
}

// ---------------------------------------------------------------------------
// LOW-REG GEMM block (layer 0 only, hidden under adj scan, fp32, ~42 regs)
// ---------------------------------------------------------------------------
__device__ __forceinline__ void gemm_block_small(
    const float* __restrict__ A,
    const float* __restrict__ Wl, const float* __restrict__ Wr,
    const float* __restrict__ bias, int rb, int cb,
    float (*As)[64], float (*Bs)[64])
{
    const int fout = 128;
    int tid = threadIdx.x;
    int rowBase = rb * 64;
    int vcol = cb * 64;

    const float* B;
    float* out;
    int colBase;
    bool addb;
    if (vcol < fout) { B = Wl; out = g_z; colBase = vcol;        addb = false; }
    else             { B = Wr; out = g_r; colBase = vcol - fout; addb = true;  }

    int tx = tid & 15;
    int ty = tid >> 4;

    float acc[4][4];
#pragma unroll
    for (int i = 0; i < 4; i++)
#pragma unroll
        for (int j = 0; j < 4; j++) acc[i][j] = 0.0f;

#pragma unroll 1
    for (int kt = 0; kt < 4; kt++) {
        int koff = kt * 32;
#pragma unroll
        for (int i = 0; i < 2; i++) {
            int lin = tid + i * 256;
            int m = lin >> 3;
            int kq = lin & 7;
            float4 v = *reinterpret_cast<const float4*>(
                &A[(size_t)(rowBase + m) * 128 + koff + kq * 4]);
            As[kq * 4 + 0][m] = v.x;
            As[kq * 4 + 1][m] = v.y;
            As[kq * 4 + 2][m] = v.z;
            As[kq * 4 + 3][m] = v.w;
        }
#pragma unroll
        for (int i = 0; i < 2; i++) {
            int lin = tid + i * 256;
            int o = lin >> 3;
            int kq = lin & 7;
            float4 v = *reinterpret_cast<const float4*>(
                &B[(size_t)(colBase + o) * 128 + koff + kq * 4]);
            Bs[kq * 4 + 0][o] = v.x;
            Bs[kq * 4 + 1][o] = v.y;
            Bs[kq * 4 + 2][o] = v.z;
            Bs[kq * 4 + 3][o] = v.w;
        }
        __syncthreads();

#pragma unroll
        for (int kk = 0; kk < 32; kk++) {
            float4 a0 = *reinterpret_cast<float4*>(&As[kk][ty * 4]);
            float4 b0 = *reinterpret_cast<float4*>(&Bs[kk][tx * 4]);
            float am[4] = {a0.x, a0.y, a0.z, a0.w};
            float bn[4] = {b0.x, b0.y, b0.z, b0.w};
#pragma unroll
            for (int i = 0; i < 4; i++)
#pragma unroll
                for (int j = 0; j < 4; j++)
                    acc[i][j] = fmaf(am[i], bn[j], acc[i][j]);
        }
        __syncthreads();
    }

#pragma unroll
    for (int i = 0; i < 4; i++) {
        int m = rowBase + ty * 4 + i;
        int o = colBase + tx * 4;
        float4 v;
        v.x = acc[i][0]; v.y = acc[i][1]; v.z = acc[i][2]; v.w = acc[i][3];
        if (addb) {
            float4 bv = *reinterpret_cast<const float4*>(&bias[o]);
            v.x += bv.x; v.y += bv.y; v.z += bv.z; v.w += bv.w;
        }
        *reinterpret_cast<float4*>(&out[(size_t)m * fout + o]) = v;
    }
}

// ---------------------------------------------------------------------------
// Fused kernel (R11-proven): blocks [0,1024) = layer-0 transform (lean regs);
// blocks [1024, 1024+32768) scan the 1 GB adj (32 KB contiguous per block).
// ---------------------------------------------------------------------------
__global__ void __launch_bounds__(256) fused_gemm0_build_kernel(
    const float* __restrict__ x, const float* __restrict__ adj,
    const float* __restrict__ Wl0, const float* __restrict__ Wr0,
    const float* __restrict__ b0)
{
    __shared__ float As[32][64];
    __shared__ float Bs[32][64];

    int bid = blockIdx.x;
    if (bid < 1024) {
        gemm_block_small(x, Wl0, Wr0, b0, bid >> 2, bid & 3, As, Bs);
        return;
    }

    int bb = bid - 1024;
    const float4* adj4 = reinterpret_cast<const float4*>(adj);
    size_t base = (size_t)bb * 2048 + threadIdx.x;

    float4 v[8];
#pragma unroll
    for (int i = 0; i < 8; i++) v[i] = __ldcs(&adj4[base + (size_t)i * 256]);

#pragma unroll
    for (int i = 0; i < 8; i++) {
        size_t idx = base + (size_t)i * 256;
        int r  = (int)(idx >> 12);          // 4096 float4 per adj row
        int c0 = (int)((idx & 4095) << 2);
        if (v[i].x != 0.0f) { int s = atomicAdd(&g_cnt[c0 + 0], 1); if (s < CAP) g_nbr[(c0 + 0) * CAP + s] = r; }
        if (v[i].y != 0.0f) { int s = atomicAdd(&g_cnt[c0 + 1], 1); if (s < CAP) g_nbr[(c0 + 1) * CAP + s] = r; }
        if (v[i].z != 0.0f) { int s = atomicAdd(&g_cnt[c0 + 2], 1); if (s < CAP) g_nbr[(c0 + 2) * CAP + s] = r; }
        if (v[i].w != 0.0f) { int s = atomicAdd(&g_cnt[c0 + 3], 1); if (s < CAP) g_nbr[(c0 + 3) * CAP + s] = r; }
    }
}

// ---------------------------------------------------------------------------
// tf32 helpers
// ---------------------------------------------------------------------------
__device__ __forceinline__ uint32_t f2tf32(float x) {
    uint32_t r;
    asm("cvt.rna.tf32.f32 %0, %1;" : "=r"(r) : "f"(x));
    return r;
}

// Split o into (hi tf32, lo residual fp32-bits). Same numerics as R15.
__device__ __forceinline__ uint2 splitf(float o) {
    uint32_t h = f2tf32(o);
    return make_uint2(h, __float_as_uint(o - __uint_as_float(h)));
}

__device__ __forceinline__ void mma_tf32(float* c,
    uint32_t a0, uint32_t a1, uint32_t a2, uint32_t a3,
    uint32_t b0, uint32_t b1)
{
    asm volatile(
        "mma.sync.aligned.m16n8k8.row.col.f32.tf32.tf32.f32 "
        "{%0,%1,%2,%3}, {%4,%5,%6,%7}, {%8,%9}, {%0,%1,%2,%3};\n"
        : "+f"(c[0]), "+f"(c[1]), "+f"(c[2]), "+f"(c[3])
        : "r"(a0), "r"(a1), "r"(a2), "r"(a3), "r"(b0), "r"(b1));
}

// ---------------------------------------------------------------------------
// TF32 GEMM (layers 1 & 2), 3xTF32 split; hi/lo converted ONCE at staging
// and stored packed (uint2) in smem -> inner loop = pure LDS.64 + MMA.
// Tile 128 rows x 64 virtual cols, K=128 as 8 k-tiles of BK=16.
// Warps 4(m) x 2(n); warp tile 32x32 = (2 mt) x (4 nt) m16n8k8 frags.
// Row stride 20 uint2: frag addr ≡ lane (mod 16) -> conflict-free.
// Smem 30.7 KB static -> 2 CTAs/SM.
// ---------------------------------------------------------------------------
__global__ void __launch_bounds__(256, 2) gemm_tf32_kernel(
    const float* __restrict__ Wl, const float* __restrict__ Wr,
    const float* __restrict__ bias, int fout)
{
    __shared__ __align__(16) uint2 As2[128][20];
    __shared__ __align__(16) uint2 Bs2[64][20];

    int tid = threadIdx.x;
    int rowBase = blockIdx.x * 128;
    int cbase = blockIdx.y * 64;

    int w = tid >> 5, lane = tid & 31;
    int g = lane >> 2, t4 = lane & 3;
    int warpM = (w >> 1) * 32;
    int warpN = (w & 1) * 32;

    // Staging source/dest: A = 512 float4/tile (2/thread), B = 256 (1/thread).
    const float* aSrc[2];
    uint2* aDst[2];
#pragma unroll
    for (int i = 0; i < 2; i++) {
        int lin = tid + i * 256;
        int row = lin >> 2, kq = lin & 3;
        aSrc[i] = g_h + (size_t)(rowBase + row) * 128 + kq * 4;
        aDst[i] = &As2[row][kq * 4];
    }
    const float* bSrc;
    uint2* bDst;
    {
        int n = tid >> 2, kq = tid & 3;
        int ov = cbase + n;
        const float* bp = (ov < fout) ? (Wl + (size_t)ov * 128)
                                      : (Wr + (size_t)(ov - fout) * 128);
        bSrc = bp + kq * 4;
        bDst = &Bs2[n][kq * 4];
    }

    float c[2][4][4];
#pragma unroll
    for (int mt = 0; mt < 2; mt++)
#pragma unroll
        for (int nt = 0; nt < 4; nt++)
#pragma unroll
            for (int q = 0; q < 4; q++) c[mt][nt][q] = 0.0f;

    float4 pa0 = *reinterpret_cast<const float4*>(aSrc[0]);
    float4 pa1 = *reinterpret_cast<const float4*>(aSrc[1]);
    float4 pbv = *reinterpret_cast<const float4*>(bSrc);

    // Store one staged float4 as 2x uint4 (packed hi/lo pairs).
    auto store_split = [](uint2* dst, float4 v) {
        uint2 s0 = splitf(v.x), s1 = splitf(v.y), s2 = splitf(v.z), s3 = splitf(v.w);
        *reinterpret_cast<uint4*>(dst)     = make_uint4(s0.x, s0.y, s1.x, s1.y);
        *reinterpret_cast<uint4*>(dst + 2) = make_uint4(s2.x, s2.y, s3.x, s3.y);
    };

    store_split(aDst[0], pa0);
    store_split(aDst[1], pa1);
    store_split(bDst, pbv);
    __syncthreads();

#pragma unroll 1
    for (int kt = 0; kt < 8; kt++) {
        if (kt < 7) {
            pa0 = *reinterpret_cast<const float4*>(aSrc[0] + (kt + 1) * 16);
            pa1 = *reinterpret_cast<const float4*>(aSrc[1] + (kt + 1) * 16);
            pbv = *reinterpret_cast<const float4*>(bSrc + (kt + 1) * 16);
        }

#pragma unroll
        for (int ks = 0; ks < 2; ks++) {
            int k0 = ks * 8 + t4;

            uint2 a0[2], a1[2], a2[2], a3[2];
#pragma unroll
            for (int mt = 0; mt < 2; mt++) {
                int m = warpM + mt * 16 + g;
                a0[mt] = As2[m][k0];
                a1[mt] = As2[m + 8][k0];
                a2[mt] = As2[m][k0 + 4];
                a3[mt] = As2[m + 8][k0 + 4];
            }
            uint2 b0[4], b1[4];
#pragma unroll
            for (int nt = 0; nt < 4; nt++) {
                int n = warpN + nt * 8 + g;
                b0[nt] = Bs2[n][k0];
                b1[nt] = Bs2[n][k0 + 4];
            }

#pragma unroll
            for (int mt = 0; mt < 2; mt++)
#pragma unroll
                for (int nt = 0; nt < 4; nt++) {
                    // ah*bl + al*bh + ah*bh (3M split; al*bl dropped)
                    mma_tf32(c[mt][nt], a0[mt].x, a1[mt].x, a2[mt].x, a3[mt].x,
                             b0[nt].y, b1[nt].y);
                    mma_tf32(c[mt][nt], a0[mt].y, a1[mt].y, a2[mt].y, a3[mt].y,
                             b0[nt].x, b1[nt].x);
                    mma_tf32(c[mt][nt], a0[mt].x, a1[mt].x, a2[mt].x, a3[mt].x,
                             b0[nt].x, b1[nt].x);
                }
        }

        if (kt < 7) {
            __syncthreads();
            store_split(aDst[0], pa0);
            store_split(aDst[1], pa1);
            store_split(bDst, pbv);
            __syncthreads();
        }
    }

    // Epilogue: c[mt][nt] -> (row, vcol) with z/r routing (+bias on r half).
#pragma unroll
    for (int mt = 0; mt < 2; mt++) {
#pragma unroll
        for (int nt = 0; nt < 4; nt++) {
            int row0 = rowBase + warpM + mt * 16 + g;
            int vcol = cbase + warpN + nt * 8 + t4 * 2;
            bool isR = (vcol >= fout);
            int col = isR ? (vcol - fout) : vcol;
            float* dst = isR ? g_r : g_z;
            float b0v = 0.f, b1v = 0.f;
            if (isR) { b0v = bias[col]; b1v = bias[col + 1]; }
            float2 v0 = make_float2(c[mt][nt][0] + b0v, c[mt][nt][1] + b1v);
            float2 v1 = make_float2(c[mt][nt][2] + b0v, c[mt][nt][3] + b1v);
            *reinterpret_cast<float2*>(&dst[(size_t)row0 * fout + col]) = v0;
            *reinterpret_cast<float2*>(&dst[(size_t)(row0 + 8) * fout + col]) = v1;
        }
    }
}

__device__ __forceinline__ float4 f4add(float4 a, float4 b) {
    return make_float4(a.x + b.x, a.y + b.y, a.z + b.z, a.w + b.w);
}

// ---------------------------------------------------------------------------
// Gather: h[t] = act( deginv[t] * sum_{n in nbr(t)} z[n]  +  r[t] )
// ---------------------------------------------------------------------------
template <int F, bool RELU>
__global__ void gather_kernel(float* __restrict__ out_ext, int sel_out) {
    constexpr int TPT = F / 4;
    constexpr int TGT_PER_BLK = 128 / TPT;

    float* out = (sel_out == 0) ? out_ext : g_h;
    int lin = threadIdx.x;
    int t = blockIdx.x * TGT_PER_BLK + lin / TPT;
    int c = lin % TPT;

    int deg = min(g_cnt[t], CAP);
    const int* nb = &g_nbr[t * CAP];
    const float4* z4 = reinterpret_cast<const float4*>(g_z);

    float4 s = make_float4(0.f, 0.f, 0.f, 0.f);
    int i = 0;
    for (; i + 4 <= deg; i += 4) {
        int4 nn = *reinterpret_cast<const int4*>(&nb[i]);
        float4 a = z4[(size_t)nn.x * TPT + c];
        float4 b = z4[(size_t)nn.y * TPT + c];
        float4 cc = z4[(size_t)nn.z * TPT + c];
        float4 d = z4[(size_t)nn.w * TPT + c];
        s = f4add(s, f4add(f4add(a, b), f4add(cc, d)));
    }
    for (; i < deg; i++)
        s = f4add(s, z4[(size_t)nb[i] * TPT + c]);

    float dinv = (deg > 0) ? (1.0f / (float)deg) : 0.0f;
    float4 rr = reinterpret_cast<const float4*>(g_r)[(size_t)t * TPT + c];
    float4 o;
    o.x = s.x * dinv + rr.x;
    o.y = s.y * dinv + rr.y;
    o.z = s.z * dinv + rr.z;
    o.w = s.w * dinv + rr.w;
    if (RELU) {
        o.x = fmaxf(o.x, 0.f); o.y = fmaxf(o.y, 0.f);
        o.z = fmaxf(o.z, 0.f); o.w = fmaxf(o.w, 0.f);
    }
    reinterpret_cast<float4*>(out)[(size_t)t * TPT + c] = o;
}

extern "C" void kernel_launch(void* const* d_in, const int* in_sizes, int n_in,
                              void* d_out, int out_size) {
    const float* x   = (const float*)d_in[0];
    const float* adj = (const float*)d_in[1];
    const float* Wl0 = (const float*)d_in[2];
    const float* b0  = (const float*)d_in[3];
    const float* Wr0 = (const float*)d_in[4];
    const float* Wl1 = (const float*)d_in[5];
    const float* b1  = (const float*)d_in[6];
    const float* Wr1 = (const float*)d_in[7];
    const float* Wl2 = (const float*)d_in[8];
    const float* b2  = (const float*)d_in[9];
    const float* Wr2 = (const float*)d_in[10];
    float* out = (float*)d_out;

    zero_cnt_kernel<<<NN / 256, 256>>>();

    // Layer-0 transform (x -> z,r) overlapped with adjacency scan (lean regs).
    fused_gemm0_build_kernel<<<1024 + 32768, 256>>>(x, adj, Wl0, Wr0, b0);

    // Layer 0 aggregate+activate: g_h = relu(mean(z) + r)
    gather_kernel<128, true><<<NN / 4, 128>>>(nullptr, 1);

    // Layer 1 (virtual cols = 256 -> 4 col blocks of 64), tf32 tensor cores
    gemm_tf32_kernel<<<dim3(NN / 128, 4), 256>>>(Wl1, Wr1, b1, 128);
    gather_kernel<128, true><<<NN / 4, 128>>>(nullptr, 1);

    // Layer 2 (fout = 64, virtual cols = 128 -> 2 col blocks), tf32
    gemm_tf32_kernel<<<dim3(NN / 128, 2), 256>>>(Wl2, Wr2, b2, 64);
    gather_kernel<64, false><<<NN / 8, 128>>>(out, 0);
}